// round 6
// baseline (speedup 1.0000x reference)
#include <cuda_runtime.h>
#include <math.h>

// ---------------- problem constants ----------------
#define V_SZ   32000
#define M_SZ   512
#define NLEAF  16384
#define D_SZ   8
#define N_SZ   4096
#define K_CH   4
#define B_SZ   64
#define S_SZ   16
#define POOL_SZ (1 + NLEAF + D_SZ * N_SZ)   // 49153

// ---------------- device scratch (no cudaMalloc allowed) ----------------
__device__ float g_c_pool[POOL_SZ * M_SZ];
__device__ float g_h_pool[POOL_SZ * M_SZ];
__device__ float g_hsum[N_SZ * M_SZ];
__device__ float g_iou[N_SZ * 3 * M_SZ];
__device__ float g_fx[N_SZ * M_SZ];
__device__ float g_fh[N_SZ * K_CH * M_SZ];
__device__ float g_xs[B_SZ * S_SZ * M_SZ];
__device__ float g_xg_f[B_SZ * S_SZ * 3 * M_SZ];
__device__ float g_xg_b[B_SZ * S_SZ * 3 * M_SZ];
__device__ float g_hbuf[2][2][B_SZ * M_SZ];      // [pingpong][dir]
__device__ float g_fwd[B_SZ * S_SZ * M_SZ];
__device__ float g_bwd[B_SZ * S_SZ * M_SZ];
__device__ float g_wt[4][M_SZ * 3 * M_SZ];       // wihT_f, whhT_f, wihT_b, whhT_b

__device__ __forceinline__ float sigf(float x) { return 1.f / (1.f + __expf(-x)); }

// ---------------- generic SGEMM: C[M,N] = gatherA(M,K) @ B(K,N) (+bias) ----------------
// 128x128 block tile, 8x8 per-thread tile, BK=8, 256 threads.
__global__ __launch_bounds__(256) void sgemm_kernel(
    const float* __restrict__ A, const int* __restrict__ gidx,
    const float* __restrict__ B, float* __restrict__ C,
    const float* __restrict__ bias, int Ndim, int Kdim)
{
    __shared__ float As[8][128];
    __shared__ float Bs[8][128];

    const int tid = threadIdx.x;
    const int rowbase  = blockIdx.y * 128;
    const int colblock = blockIdx.x * 128;

    const int arow = tid >> 1;
    const int acol = (tid & 1) * 4;
    int agrow = rowbase + arow;
    if (gidx) agrow = gidx[agrow];
    const float* Ap = A + (size_t)agrow * Kdim + acol;

    const int brow = tid >> 5;
    const int bcol = (tid & 31) << 2;
    const float* Bp = B + (size_t)brow * Ndim + colblock + bcol;

    const int tx = tid & 15;
    const int ty = tid >> 4;

    float accv[8][8];
#pragma unroll
    for (int i = 0; i < 8; i++)
#pragma unroll
        for (int j = 0; j < 8; j++) accv[i][j] = 0.f;

    float4 av = *(const float4*)Ap;
    float4 bv = *(const float4*)Bp;

    for (int kk = 0; kk < Kdim; kk += 8) {
        As[acol + 0][arow] = av.x;
        As[acol + 1][arow] = av.y;
        As[acol + 2][arow] = av.z;
        As[acol + 3][arow] = av.w;
        *(float4*)&Bs[brow][bcol] = bv;
        __syncthreads();

        if (kk + 8 < Kdim) {
            Ap += 8;
            Bp += (size_t)8 * Ndim;
            av = *(const float4*)Ap;
            bv = *(const float4*)Bp;
        }

#pragma unroll
        for (int k = 0; k < 8; k++) {
            float4 a0 = *(const float4*)&As[k][ty * 8];
            float4 a1 = *(const float4*)&As[k][ty * 8 + 4];
            float4 b0 = *(const float4*)&Bs[k][tx * 8];
            float4 b1 = *(const float4*)&Bs[k][tx * 8 + 4];
            float a[8] = {a0.x, a0.y, a0.z, a0.w, a1.x, a1.y, a1.z, a1.w};
            float b[8] = {b0.x, b0.y, b0.z, b0.w, b1.x, b1.y, b1.z, b1.w};
#pragma unroll
            for (int i = 0; i < 8; i++)
#pragma unroll
                for (int j = 0; j < 8; j++) accv[i][j] += a[i] * b[j];
        }
        __syncthreads();
    }

    const int colbase = colblock + tx * 8;
#pragma unroll
    for (int i = 0; i < 8; i++) {
        const size_t row = rowbase + ty * 8 + i;
        float* cp = C + row * Ndim + colbase;
#pragma unroll
        for (int j2 = 0; j2 < 2; j2++) {
            float4 v = make_float4(accv[i][j2 * 4], accv[i][j2 * 4 + 1],
                                   accv[i][j2 * 4 + 2], accv[i][j2 * 4 + 3]);
            if (bias) {
                const float* bp = bias + colbase + j2 * 4;
                v.x += bp[0]; v.y += bp[1]; v.z += bp[2]; v.w += bp[3];
            }
            *(float4*)(cp + j2 * 4) = v;
        }
    }
}

// ---------------- fused iou GEMM: iou = [x | hsum] @ [Wx ; Wh] + bx + bh ----------------
// A: k<512 -> embed[lidx[row]][k], k>=512 -> g_hsum[row][k-512]. K=1024, N=1536.
__global__ __launch_bounds__(256) void iou_gemm_kernel(
    const float* __restrict__ embed, const int* __restrict__ lidx,
    const float* __restrict__ Wx, const float* __restrict__ Wh,
    const float* __restrict__ bx, const float* __restrict__ bh)
{
    const int NDIM = 1536;
    __shared__ float As[8][128];
    __shared__ float Bs[8][128];

    const int tid = threadIdx.x;
    const int rowbase  = blockIdx.y * 128;
    const int colblock = blockIdx.x * 128;

    const int arow = tid >> 1;              // 0..127
    const int acol = (tid & 1) * 4;         // 0 or 4
    const int node = rowbase + arow;
    const float* AxP = embed + (size_t)lidx[node] * M_SZ + acol;   // x source
    const float* AhP = g_hsum + (size_t)node * M_SZ + acol;        // hsum source

    const int brow = tid >> 5;              // 0..7
    const int bcol = (tid & 31) << 2;       // 0..124
    const int bc = colblock + bcol;

    const int tx = tid & 15;
    const int ty = tid >> 4;

    float accv[8][8];
#pragma unroll
    for (int i = 0; i < 8; i++)
#pragma unroll
        for (int j = 0; j < 8; j++) accv[i][j] = 0.f;

    float4 av = *(const float4*)AxP;
    float4 bv = *(const float4*)(Wx + (size_t)brow * NDIM + bc);

    for (int kk = 0; kk < 1024; kk += 8) {
        As[acol + 0][arow] = av.x;
        As[acol + 1][arow] = av.y;
        As[acol + 2][arow] = av.z;
        As[acol + 3][arow] = av.w;
        *(float4*)&Bs[brow][bcol] = bv;
        __syncthreads();

        if (kk + 8 < 1024) {
            const int kn = kk + 8;
            av = (kn < 512) ? *(const float4*)(AxP + kn)
                            : *(const float4*)(AhP + (kn - 512));
            const int kb = kn + brow;
            bv = (kb < 512) ? *(const float4*)(Wx + (size_t)kb * NDIM + bc)
                            : *(const float4*)(Wh + (size_t)(kb - 512) * NDIM + bc);
        }

#pragma unroll
        for (int k = 0; k < 8; k++) {
            float4 a0 = *(const float4*)&As[k][ty * 8];
            float4 a1 = *(const float4*)&As[k][ty * 8 + 4];
            float4 b0 = *(const float4*)&Bs[k][tx * 8];
            float4 b1 = *(const float4*)&Bs[k][tx * 8 + 4];
            float a[8] = {a0.x, a0.y, a0.z, a0.w, a1.x, a1.y, a1.z, a1.w};
            float b[8] = {b0.x, b0.y, b0.z, b0.w, b1.x, b1.y, b1.z, b1.w};
#pragma unroll
            for (int i = 0; i < 8; i++)
#pragma unroll
                for (int j = 0; j < 8; j++) accv[i][j] += a[i] * b[j];
        }
        __syncthreads();
    }

    const int colbase = colblock + tx * 8;
#pragma unroll
    for (int i = 0; i < 8; i++) {
        const size_t row = rowbase + ty * 8 + i;
        float* cp = g_iou + row * NDIM + colbase;
#pragma unroll
        for (int j2 = 0; j2 < 2; j2++) {
            const int cb = colbase + j2 * 4;
            float4 v = make_float4(accv[i][j2 * 4] + bx[cb + 0] + bh[cb + 0],
                                   accv[i][j2 * 4 + 1] + bx[cb + 1] + bh[cb + 1],
                                   accv[i][j2 * 4 + 2] + bx[cb + 2] + bh[cb + 2],
                                   accv[i][j2 * 4 + 3] + bx[cb + 3] + bh[cb + 3]);
            *(float4*)(cp + j2 * 4) = v;
        }
    }
}

// ---------------- fused fx+fh GEMM (one launch, N=K=512 compile-time) ----------------
// blockIdx.y <  32 : fx rows — A = embed[lidx[row]],    B = W_fx, bias b_fx, C = g_fx
// blockIdx.y >= 32 : fh rows — A = h_pool[cidx[row]],   B = W_fh, bias b_fh, C = g_fh
__global__ __launch_bounds__(256) void fxfh_gemm_kernel(
    const float* __restrict__ embed, const int* __restrict__ lidx,
    const int* __restrict__ cidx,
    const float* __restrict__ W_fx, const float* __restrict__ b_fx,
    const float* __restrict__ W_fh, const float* __restrict__ b_fh)
{
    const int NDIM = 512;
    __shared__ float As[8][128];
    __shared__ float Bs[8][128];

    const int tid = threadIdx.x;
    const bool is_fh = (blockIdx.y >= 32);
    const int rowbase  = (is_fh ? (blockIdx.y - 32) : blockIdx.y) * 128;
    const int colblock = blockIdx.x * 128;

    const float* Asrc = is_fh ? g_h_pool : embed;
    const int*   gmap = is_fh ? cidx : lidx;
    const float* B    = is_fh ? W_fh : W_fx;
    const float* bias = is_fh ? b_fh : b_fx;
    float*       C    = is_fh ? g_fh : g_fx;

    const int arow = tid >> 1;
    const int acol = (tid & 1) * 4;
    const float* Ap = Asrc + (size_t)gmap[rowbase + arow] * M_SZ + acol;

    const int brow = tid >> 5;
    const int bcol = (tid & 31) << 2;
    const float* Bp = B + (size_t)brow * NDIM + colblock + bcol;

    const int tx = tid & 15;
    const int ty = tid >> 4;

    float accv[8][8];
#pragma unroll
    for (int i = 0; i < 8; i++)
#pragma unroll
        for (int j = 0; j < 8; j++) accv[i][j] = 0.f;

    float4 av = *(const float4*)Ap;
    float4 bv = *(const float4*)Bp;

    for (int kk = 0; kk < 512; kk += 8) {
        As[acol + 0][arow] = av.x;
        As[acol + 1][arow] = av.y;
        As[acol + 2][arow] = av.z;
        As[acol + 3][arow] = av.w;
        *(float4*)&Bs[brow][bcol] = bv;
        __syncthreads();

        if (kk + 8 < 512) {
            Ap += 8;
            Bp += (size_t)8 * NDIM;
            av = *(const float4*)Ap;
            bv = *(const float4*)Bp;
        }

#pragma unroll
        for (int k = 0; k < 8; k++) {
            float4 a0 = *(const float4*)&As[k][ty * 8];
            float4 a1 = *(const float4*)&As[k][ty * 8 + 4];
            float4 b0 = *(const float4*)&Bs[k][tx * 8];
            float4 b1 = *(const float4*)&Bs[k][tx * 8 + 4];
            float a[8] = {a0.x, a0.y, a0.z, a0.w, a1.x, a1.y, a1.z, a1.w};
            float b[8] = {b0.x, b0.y, b0.z, b0.w, b1.x, b1.y, b1.z, b1.w};
#pragma unroll
            for (int i = 0; i < 8; i++)
#pragma unroll
                for (int j = 0; j < 8; j++) accv[i][j] += a[i] * b[j];
        }
        __syncthreads();
    }

    const int colbase = colblock + tx * 8;
#pragma unroll
    for (int i = 0; i < 8; i++) {
        const size_t row = rowbase + ty * 8 + i;
        float* cp = C + row * NDIM + colbase;
#pragma unroll
        for (int j2 = 0; j2 < 2; j2++) {
            const float* bp = bias + colbase + j2 * 4;
            float4 v = make_float4(accv[i][j2 * 4] + bp[0], accv[i][j2 * 4 + 1] + bp[1],
                                   accv[i][j2 * 4 + 2] + bp[2], accv[i][j2 * 4 + 3] + bp[3]);
            *(float4*)(cp + j2 * 4) = v;
        }
    }
}

// ---------------- leaf init: c=0, h=embed[leaf_idx] (slot 0 = zeros) ----------------
__global__ void leaf_init_kernel(const float* __restrict__ embed,
                                 const int* __restrict__ leaf_idx)
{
    int gid = blockIdx.x * blockDim.x + threadIdx.x;   // (1+NLEAF)*M
    int i = gid >> 9, m = gid & 511;
    g_c_pool[gid] = 0.f;
    g_h_pool[gid] = (i == 0) ? 0.f : embed[(size_t)leaf_idx[i - 1] * M_SZ + m];
}

// ---------------- children h sum for one level ----------------
__global__ void hsum_kernel(const int* __restrict__ cidx)
{
    int gid = blockIdx.x * blockDim.x + threadIdx.x;   // N*M
    int n = gid >> 9, m = gid & 511;
    float s = 0.f;
#pragma unroll
    for (int k = 0; k < K_CH; k++)
        s += g_h_pool[(size_t)cidx[n * K_CH + k] * M_SZ + m];
    g_hsum[gid] = s;
}

// ---------------- TreeLSTM gate combine, write level rows into pool ----------------
__global__ void combine_kernel(const int* __restrict__ cidx, int d)
{
    int gid = blockIdx.x * blockDim.x + threadIdx.x;   // N*M
    int n = gid >> 9, m = gid & 511;
    float iv = sigf(g_iou[(size_t)n * 1536 + m]);
    float ov = sigf(g_iou[(size_t)n * 1536 + 512 + m]);
    float uv = tanhf(g_iou[(size_t)n * 1536 + 1024 + m]);
    float fx = g_fx[gid];
    float c = iv * uv;
#pragma unroll
    for (int k = 0; k < K_CH; k++) {
        float f = sigf(fx + g_fh[(size_t)(n * K_CH + k) * M_SZ + m]);
        c += f * g_c_pool[(size_t)cidx[n * K_CH + k] * M_SZ + m];
    }
    float h = ov * tanhf(c);
    size_t row = (size_t)(1 + NLEAF) + (size_t)d * N_SZ + n;
    g_c_pool[row * M_SZ + m] = c;
    g_h_pool[row * M_SZ + m] = h;
}

// ---------------- batched weight transpose: 4 x (3M,M) -> (M,3M) ----------------
__global__ void transpose4_kernel(const float* __restrict__ s0, const float* __restrict__ s1,
                                  const float* __restrict__ s2, const float* __restrict__ s3)
{
    int g = blockIdx.x * blockDim.x + threadIdx.x;  // 1536*512 per slice
    const float* src = (blockIdx.y == 0) ? s0 : (blockIdx.y == 1) ? s1
                     : (blockIdx.y == 2) ? s2 : s3;
    int r = g / 512, c = g % 512;
    g_wt[blockIdx.y][(size_t)c * 1536 + r] = src[g];
}

// ---------------- xs = h_pool[context_idx] ----------------
__global__ void xs_gather_kernel(const int* __restrict__ ctx)
{
    int gid = blockIdx.x * blockDim.x + threadIdx.x;  // B*S*M
    int t = gid >> 9, m = gid & 511;
    g_xs[gid] = g_h_pool[(size_t)ctx[t] * M_SZ + m];
}

// ---------------- zero GRU hidden state buffers ----------------
__global__ void hzero_kernel()
{
    int gid = blockIdx.x * blockDim.x + threadIdx.x;  // 2*2*B*M
    ((float*)g_hbuf)[gid] = 0.f;
}

// ---------------- one GRU step, both directions fused ----------------
__global__ __launch_bounds__(256) void gru_step_kernel(
    int step, const float* __restrict__ bhh_f, const float* __restrict__ bhh_b)
{
    int gid = blockIdx.x * blockDim.x + threadIdx.x;  // 2*B*M = 65536
    int dir = gid >> 15;
    int r = gid & 32767;
    int b = r >> 9;
    int m = r & 511;

    const float* hin = g_hbuf[step & 1][dir] + b * M_SZ;
    const float* wT  = g_wt[dir ? 3 : 1];
    const float* bhh = dir ? bhh_b : bhh_f;

    float hr = bhh[m], hz = bhh[512 + m], hn = bhh[1024 + m];
#pragma unroll 4
    for (int k = 0; k < M_SZ; k++) {
        float hp = hin[k];
        const float* w = wT + (size_t)k * 1536 + m;
        hr += hp * w[0];
        hz += hp * w[512];
        hn += hp * w[1024];
    }
    int pos = dir ? (S_SZ - 1 - step) : step;
    const float* xg = (dir ? g_xg_b : g_xg_f) + (size_t)(b * S_SZ + pos) * 1536;
    float rr = sigf(xg[m] + hr);
    float zz = sigf(xg[512 + m] + hz);
    float nn = tanhf(xg[1024 + m] + rr * hn);
    float hnew = (1.f - zz) * nn + zz * hin[m];
    g_hbuf[(step + 1) & 1][dir][b * M_SZ + m] = hnew;
    (dir ? g_bwd : g_fwd)[(size_t)(b * S_SZ + pos) * M_SZ + m] = hnew;
}

// ---------------- out = fwd + bwd ----------------
__global__ void final_add_kernel(float* __restrict__ out)
{
    int gid = blockIdx.x * blockDim.x + threadIdx.x;  // B*S*M
    out[gid] = g_fwd[gid] + g_bwd[gid];
}

// ---------------- host driver ----------------
extern "C" void kernel_launch(void* const* d_in, const int* in_sizes, int n_in,
                              void* d_out, int out_size)
{
    (void)out_size;
    const float* embed   = (const float*)d_in[0];
    const float* W_ioux  = (const float*)d_in[1];
    const float* b_ioux  = (const float*)d_in[2];
    const float* W_iouh  = (const float*)d_in[3];
    const float* b_iouh  = (const float*)d_in[4];
    const float* W_fx    = (const float*)d_in[5];
    const float* b_fx    = (const float*)d_in[6];
    const float* W_fh    = (const float*)d_in[7];
    const float* b_fh    = (const float*)d_in[8];
    const float* wih_f   = (const float*)d_in[9];
    const float* whh_f   = (const float*)d_in[10];
    const float* bih_f   = (const float*)d_in[11];
    const float* bhh_f   = (const float*)d_in[12];
    const float* wih_b   = (const float*)d_in[13];
    const float* whh_b   = (const float*)d_in[14];
    const float* bih_b   = (const float*)d_in[15];
    const float* bhh_b   = (const float*)d_in[16];

    // int32 inputs resolved BY SIZE (dict order vs signature order differ for child/context)
    const int *leaf_idx = nullptr, *level_idx = nullptr, *ctx_idx = nullptr, *child_idx = nullptr;
    for (int i = 17; i < n_in; i++) {
        switch (in_sizes[i]) {
            case NLEAF:              leaf_idx  = (const int*)d_in[i]; break;  // 16384
            case D_SZ * N_SZ:        level_idx = (const int*)d_in[i]; break;  // 32768
            case B_SZ * S_SZ:        ctx_idx   = (const int*)d_in[i]; break;  // 1024
            case D_SZ * N_SZ * K_CH: child_idx = (const int*)d_in[i]; break;  // 131072
        }
    }
    float* out = (float*)d_out;

    float *p_xs, *p_xg_f, *p_xg_b, *p_wt;
    cudaGetSymbolAddress((void**)&p_xs,   g_xs);
    cudaGetSymbolAddress((void**)&p_xg_f, g_xg_f);
    cudaGetSymbolAddress((void**)&p_xg_b, g_xg_b);
    cudaGetSymbolAddress((void**)&p_wt,   g_wt);

    const int T = 256;

    // 1) leaves
    leaf_init_kernel<<<((1 + NLEAF) * M_SZ) / T, T>>>(embed, leaf_idx);

    // 2) tree levels (level-synchronous)
    for (int d = 0; d < D_SZ; d++) {
        const int* cidx = child_idx + d * N_SZ * K_CH;
        const int* lidx = level_idx + d * N_SZ;

        hsum_kernel<<<(N_SZ * M_SZ) / T, T>>>(cidx);

        // iou = [x | hsum] @ [W_ioux ; W_iouh] + b_ioux + b_iouh  (fused, K=1024)
        iou_gemm_kernel<<<dim3(12, 32), T>>>(embed, lidx, W_ioux, W_iouh, b_ioux, b_iouh);
        // fx and fh in ONE launch (640 blocks)
        fxfh_gemm_kernel<<<dim3(4, 160), T>>>(embed, lidx, cidx, W_fx, b_fx, W_fh, b_fh);

        combine_kernel<<<(N_SZ * M_SZ) / T, T>>>(cidx, d);
    }

    // 3) GRU: batched weight transpose, precompute input gates
    transpose4_kernel<<<dim3((1536 * 512) / T, 4), T>>>(wih_f, whh_f, wih_b, whh_b);

    xs_gather_kernel<<<(B_SZ * S_SZ * M_SZ) / T, T>>>(ctx_idx);

    sgemm_kernel<<<dim3(12, 8), T>>>(p_xs, nullptr, p_wt + 0 * M_SZ * 1536, p_xg_f, bih_f, 1536, 512);
    sgemm_kernel<<<dim3(12, 8), T>>>(p_xs, nullptr, p_wt + 2 * M_SZ * 1536, p_xg_b, bih_b, 1536, 512);

    hzero_kernel<<<(2 * 2 * B_SZ * M_SZ) / T, T>>>();

    // 4) 16 recurrent steps, both directions fused per step
    for (int t = 0; t < S_SZ; t++)
        gru_step_kernel<<<(2 * B_SZ * M_SZ) / T, T>>>(t, bhh_f, bhh_b);

    // 5) out = fwd + bwd
    final_add_kernel<<<(B_SZ * S_SZ * M_SZ) / T, T>>>(out);
}